// round 3
// baseline (speedup 1.0000x reference)
#include <cuda_runtime.h>
#include <cstddef>

#define BATCH 8
#define CIN 64
#define NPTS 4096
#define COUT 64
#define KNN 20
#define TN 128
#define TM 64

// scratch (device globals: no allocations allowed)
__device__ float g_y2p[(size_t)BATCH * NPTS * COUT];  // a*(x . W2)
__device__ float g_zp [(size_t)BATCH * NPTS * COUT];  // a*(x . (W1-W2)) + beta - a*mean
__device__ float g_xx [(size_t)BATCH * NPTS];         // ||x_n||^2

// ---------------------------------------------------------------------------
// Kernel A: per-point projections + BN folding + ||x||^2
// ---------------------------------------------------------------------------
__global__ void __launch_bounds__(128) prep_kernel(
    const float* __restrict__ x, const float* __restrict__ W,
    const float* __restrict__ gamma, const float* __restrict__ beta,
    const float* __restrict__ rmean, const float* __restrict__ rvar)
{
    __shared__ float sW[COUT * 2 * CIN];   // 64 x 128
    __shared__ float sA[COUT], sC0[COUT];

    const int t = threadIdx.x;
    const int b = blockIdx.y;
    const int n = blockIdx.x * 128 + t;

    // load W (8192 floats = 2048 float4)
    for (int i = t; i < 2048; i += 128)
        ((float4*)sW)[i] = ((const float4*)W)[i];
    if (t < COUT) {
        float a = rsqrtf(rvar[t] + 1e-5f) * gamma[t];
        sA[t] = a;
        sC0[t] = fmaf(-a, rmean[t], beta[t]);
    }
    __syncthreads();

    const float* xb = x + (size_t)b * CIN * NPTS;
    float xq[CIN];
#pragma unroll
    for (int c = 0; c < CIN; c++) xq[c] = xb[(size_t)c * NPTS + n];

    float xx = 0.f;
#pragma unroll
    for (int c = 0; c < CIN; c++) xx = fmaf(xq[c], xq[c], xx);
    g_xx[(size_t)b * NPTS + n] = xx;

    float* y2r = g_y2p + ((size_t)b * NPTS + n) * COUT;
    float* zr  = g_zp  + ((size_t)b * NPTS + n) * COUT;

#pragma unroll 1
    for (int o = 0; o < COUT; o++) {
        const float* wr = sW + o * 128;
        float s2 = 0.f, sz = 0.f;
#pragma unroll
        for (int c = 0; c < 16; c++) {
            float4 w1 = *(const float4*)(wr + c * 4);
            float4 w2 = *(const float4*)(wr + 64 + c * 4);
            float q0 = xq[4*c+0], q1 = xq[4*c+1], q2 = xq[4*c+2], q3 = xq[4*c+3];
            s2 = fmaf(q0, w2.x, s2); sz = fmaf(q0, w1.x - w2.x, sz);
            s2 = fmaf(q1, w2.y, s2); sz = fmaf(q1, w1.y - w2.y, sz);
            s2 = fmaf(q2, w2.z, s2); sz = fmaf(q2, w1.z - w2.z, sz);
            s2 = fmaf(q3, w2.w, s2); sz = fmaf(q3, w1.w - w2.w, sz);
        }
        float a = sA[o];
        y2r[o] = a * s2;
        zr[o]  = fmaf(a, sz, sC0[o]);
    }
}

// ---------------------------------------------------------------------------
// top-20 insertion: register arrays, replace current max, rescan for new max.
// scanning m ascending with strict '<' matches lax.top_k lowest-index tiebreak.
// ---------------------------------------------------------------------------
__device__ __forceinline__ void insert20(float (&td)[KNN], int (&ti)[KNN],
                                         float& kmax, int& kpos,
                                         float d, int m)
{
#pragma unroll
    for (int k = 0; k < KNN; k++) {
        if (k == kpos) { td[k] = d; ti[k] = m; }
    }
    float mx = -1e30f; int mp = 0;
#pragma unroll
    for (int k = 0; k < KNN; k++) {
        if (td[k] > mx) { mx = td[k]; mp = k; }
    }
    kmax = mx; kpos = mp;
}

// ---------------------------------------------------------------------------
// Kernel B: fused distance + top-K + gather-max + BN/leaky epilogue.
// One thread per query row n. Candidate tiles (64 pts x 64 ch) staged in smem
// transposed, consumed via broadcast LDS.128. Register-prefetch double buffer.
// ---------------------------------------------------------------------------
__global__ void __launch_bounds__(128) knn_kernel(
    const float* __restrict__ x, float* __restrict__ out)
{
    __shared__ float s_xm[TM][68];   // [m][c], padded stride (16B-aligned rows)
    __shared__ float s_xx[TM];

    const int t = threadIdx.x;
    const int b = blockIdx.y;
    const int n = blockIdx.x * TN + t;
    const float* xb = x + (size_t)b * CIN * NPTS;

    // query row in registers
    float xq[CIN];
#pragma unroll
    for (int c = 0; c < CIN; c++) xq[c] = xb[(size_t)c * NPTS + n];

    float xxq;
    {
        float s0 = 0.f, s1 = 0.f, s2 = 0.f, s3 = 0.f;
#pragma unroll
        for (int c = 0; c < CIN; c += 4) {
            s0 = fmaf(xq[c+0], xq[c+0], s0);
            s1 = fmaf(xq[c+1], xq[c+1], s1);
            s2 = fmaf(xq[c+2], xq[c+2], s2);
            s3 = fmaf(xq[c+3], xq[c+3], s3);
        }
        xxq = (s0 + s1) + (s2 + s3);
    }

    float td[KNN]; int ti[KNN];
#pragma unroll
    for (int k = 0; k < KNN; k++) { td[k] = 1e30f; ti[k] = 0; }
    float kmax = 1e30f; int kpos = 0;

    // cooperative tile loader mapping: thread -> (channel, half of m-range)
    const int lc = t >> 1;
    const int lm = (t & 1) * 32;
    const float* lptr = xb + (size_t)lc * NPTS + lm;
    const float* xxp  = g_xx + (size_t)b * NPTS;

    float4 ld[8]; float xld = 0.f;

    // prologue: tile 0
#pragma unroll
    for (int j = 0; j < 8; j++) ld[j] = *(const float4*)(lptr + 4 * j);
    if (t < TM) xld = xxp[t];
#pragma unroll
    for (int j = 0; j < 8; j++) {
        int m = lm + 4 * j;
        s_xm[m+0][lc] = ld[j].x; s_xm[m+1][lc] = ld[j].y;
        s_xm[m+2][lc] = ld[j].z; s_xm[m+3][lc] = ld[j].w;
    }
    if (t < TM) s_xx[t] = xld;
    __syncthreads();

    const int NT = NPTS / TM;   // 64 tiles
#pragma unroll 1
    for (int tile = 0; tile < NT; tile++) {
        // prefetch next tile into registers (latency hidden behind compute)
        if (tile + 1 < NT) {
            const float* p = lptr + (tile + 1) * TM;
#pragma unroll
            for (int j = 0; j < 8; j++) ld[j] = *(const float4*)(p + 4 * j);
            if (t < TM) xld = xxp[(tile + 1) * TM + t];
        }

        const int mbase = tile * TM;
#pragma unroll 1
        for (int mg = 0; mg < TM; mg += 4) {
            float a0 = 0.f, a1 = 0.f, a2 = 0.f, a3 = 0.f;
#pragma unroll
            for (int c4 = 0; c4 < 16; c4++) {
                const float4 v0 = *(const float4*)(&s_xm[mg+0][c4*4]);
                const float4 v1 = *(const float4*)(&s_xm[mg+1][c4*4]);
                const float4 v2 = *(const float4*)(&s_xm[mg+2][c4*4]);
                const float4 v3 = *(const float4*)(&s_xm[mg+3][c4*4]);
                const float q0 = xq[c4*4+0], q1 = xq[c4*4+1];
                const float q2 = xq[c4*4+2], q3 = xq[c4*4+3];
                a0 = fmaf(q0, v0.x, a0); a1 = fmaf(q0, v1.x, a1);
                a2 = fmaf(q0, v2.x, a2); a3 = fmaf(q0, v3.x, a3);
                a0 = fmaf(q1, v0.y, a0); a1 = fmaf(q1, v1.y, a1);
                a2 = fmaf(q1, v2.y, a2); a3 = fmaf(q1, v3.y, a3);
                a0 = fmaf(q2, v0.z, a0); a1 = fmaf(q2, v1.z, a1);
                a2 = fmaf(q2, v2.z, a2); a3 = fmaf(q2, v3.z, a3);
                a0 = fmaf(q3, v0.w, a0); a1 = fmaf(q3, v1.w, a1);
                a2 = fmaf(q3, v2.w, a2); a3 = fmaf(q3, v3.w, a3);
            }
            const float e0 = fmaf(a0, -2.f, xxq + s_xx[mg+0]);
            const float e1 = fmaf(a1, -2.f, xxq + s_xx[mg+1]);
            const float e2 = fmaf(a2, -2.f, xxq + s_xx[mg+2]);
            const float e3 = fmaf(a3, -2.f, xxq + s_xx[mg+3]);
            // single coarse branch; inserts rare after warm-up
            const float emin = fminf(fminf(e0, e1), fminf(e2, e3));
            if (emin < kmax) {
                if (e0 < kmax) insert20(td, ti, kmax, kpos, e0, mbase + mg + 0);
                if (e1 < kmax) insert20(td, ti, kmax, kpos, e1, mbase + mg + 1);
                if (e2 < kmax) insert20(td, ti, kmax, kpos, e2, mbase + mg + 2);
                if (e3 < kmax) insert20(td, ti, kmax, kpos, e3, mbase + mg + 3);
            }
        }
        __syncthreads();
        if (tile + 1 < NT) {
#pragma unroll
            for (int j = 0; j < 8; j++) {
                int m = lm + 4 * j;
                s_xm[m+0][lc] = ld[j].x; s_xm[m+1][lc] = ld[j].y;
                s_xm[m+2][lc] = ld[j].z; s_xm[m+3][lc] = ld[j].w;
            }
            if (t < TM) s_xx[t] = xld;
        }
        __syncthreads();
    }

    // ---- fused epilogue: out[b][o][n] = leaky(zp[n][o] + max_k y2p[idx_k][o])
    const float* y2b = g_y2p + (size_t)b * NPTS * COUT;
    float4 acc[16];
#pragma unroll
    for (int j = 0; j < 16; j++) acc[j] = make_float4(-1e30f, -1e30f, -1e30f, -1e30f);

#pragma unroll
    for (int k = 0; k < KNN; k++) {
        const float4* row = (const float4*)(y2b + (size_t)ti[k] * COUT);
#pragma unroll
        for (int j = 0; j < 16; j++) {
            float4 v = row[j];
            acc[j].x = fmaxf(acc[j].x, v.x);
            acc[j].y = fmaxf(acc[j].y, v.y);
            acc[j].z = fmaxf(acc[j].z, v.z);
            acc[j].w = fmaxf(acc[j].w, v.w);
        }
    }

    const float4* zr = (const float4*)(g_zp + ((size_t)b * NPTS + n) * COUT);
    float* ob = out + (size_t)b * COUT * NPTS + n;
#pragma unroll
    for (int j = 0; j < 16; j++) {
        float4 z = zr[j];
        float r0 = z.x + acc[j].x; r0 = (r0 >= 0.f) ? r0 : 0.2f * r0;
        float r1 = z.y + acc[j].y; r1 = (r1 >= 0.f) ? r1 : 0.2f * r1;
        float r2 = z.z + acc[j].z; r2 = (r2 >= 0.f) ? r2 : 0.2f * r2;
        float r3 = z.w + acc[j].w; r3 = (r3 >= 0.f) ? r3 : 0.2f * r3;
        ob[(size_t)(4*j+0) * NPTS] = r0;
        ob[(size_t)(4*j+1) * NPTS] = r1;
        ob[(size_t)(4*j+2) * NPTS] = r2;
        ob[(size_t)(4*j+3) * NPTS] = r3;
    }
}

// ---------------------------------------------------------------------------
extern "C" void kernel_launch(void* const* d_in, const int* in_sizes, int n_in,
                              void* d_out, int out_size)
{
    const float* x     = (const float*)d_in[0];
    const float* W     = (const float*)d_in[1];
    const float* gamma = (const float*)d_in[2];
    const float* beta  = (const float*)d_in[3];
    const float* rmean = (const float*)d_in[4];
    const float* rvar  = (const float*)d_in[5];
    float* out = (float*)d_out;

    (void)in_sizes; (void)n_in; (void)out_size;

    dim3 grid(NPTS / 128, BATCH);
    prep_kernel<<<grid, 128>>>(x, W, gamma, beta, rmean, rvar);
    knn_kernel<<<dim3(NPTS / TN, BATCH), 128>>>(x, out);
}